// round 1
// baseline (speedup 1.0000x reference)
#include <cuda_runtime.h>
#include <cuda_bf16.h>
#include <math.h>

// TemporalAttention: out[d,b] = sum_s softmax_s((enc[b,s,:]·We_w + We_b)*ut)[s] * enc[b,s,d]
// Single-pass online softmax, split over S. enc_out read exactly once from HBM.

#define D_DIM    256
#define NSPLIT   8
#define WARPS    8
#define THREADS  (WARPS * 32)
#define MAXB     128

// Per-(b,split) partial: 256 acc values + m + l
__device__ float g_scratch[MAXB * NSPLIT * (D_DIM + 2)];

__global__ __launch_bounds__(THREADS) void ta_pass1(
    const float* __restrict__ enc,
    const float* __restrict__ Ww,
    const float* __restrict__ Wb,
    const float* __restrict__ ut,
    int S)
{
    const int split = blockIdx.x;
    const int b     = blockIdx.y;
    const int w     = threadIdx.x >> 5;
    const int lane  = threadIdx.x & 31;

    // Per-lane slice of We_w (lane k owns d = 8k..8k+7)
    float wv[8];
#pragma unroll
    for (int j = 0; j < 8; j++) wv[j] = Ww[lane * 8 + j];
    const float be = Wb[0];
    const float u  = ut[0];

    const int s0   = (int)(((long long)split * S) / NSPLIT);
    const int s1   = (int)(((long long)(split + 1) * S) / NSPLIT);
    const int rows = s1 - s0;

    const float* base = enc + ((long long)b * S + s0) * D_DIM;

    float m = -1e30f;
    float l = 0.0f;
    float acc[8];
#pragma unroll
    for (int j = 0; j < 8; j++) acc[j] = 0.0f;

    // Process 2 rows per iteration per warp: 4 independent LDG.128 in flight.
    int r = w;
    for (; r + WARPS < rows; r += 2 * WARPS) {
        const float4* p0 = (const float4*)(base + (long long)r * D_DIM) + lane * 2;
        const float4* p1 = (const float4*)(base + (long long)(r + WARPS) * D_DIM) + lane * 2;
        float4 a0 = p0[0], a1 = p0[1];
        float4 b0 = p1[0], b1 = p1[1];

        float xA[8] = {a0.x, a0.y, a0.z, a0.w, a1.x, a1.y, a1.z, a1.w};
        float xB[8] = {b0.x, b0.y, b0.z, b0.w, b1.x, b1.y, b1.z, b1.w};

        float dA = 0.0f, dB = 0.0f;
#pragma unroll
        for (int j = 0; j < 8; j++) { dA = fmaf(xA[j], wv[j], dA); dB = fmaf(xB[j], wv[j], dB); }
#pragma unroll
        for (int o = 16; o > 0; o >>= 1) {
            dA += __shfl_xor_sync(0xffffffffu, dA, o);
            dB += __shfl_xor_sync(0xffffffffu, dB, o);
        }
        float sA = (dA + be) * u;
        float sB = (dB + be) * u;

        // Combined online update for two scores
        float mnew  = fmaxf(m, fmaxf(sA, sB));
        float scale = __expf(m - mnew);
        float pA    = __expf(sA - mnew);
        float pB    = __expf(sB - mnew);
        l = l * scale + pA + pB;
#pragma unroll
        for (int j = 0; j < 8; j++)
            acc[j] = fmaf(acc[j], scale, fmaf(pA, xA[j], pB * xB[j]));
        m = mnew;
    }
    // Tail (at most one row per warp)
    for (; r < rows; r += WARPS) {
        const float4* p0 = (const float4*)(base + (long long)r * D_DIM) + lane * 2;
        float4 a0 = p0[0], a1 = p0[1];
        float x[8] = {a0.x, a0.y, a0.z, a0.w, a1.x, a1.y, a1.z, a1.w};
        float d = 0.0f;
#pragma unroll
        for (int j = 0; j < 8; j++) d = fmaf(x[j], wv[j], d);
#pragma unroll
        for (int o = 16; o > 0; o >>= 1) d += __shfl_xor_sync(0xffffffffu, d, o);
        float s = (d + be) * u;
        float mnew  = fmaxf(m, s);
        float scale = __expf(m - mnew);
        float p     = __expf(s - mnew);
        l = l * scale + p;
#pragma unroll
        for (int j = 0; j < 8; j++) acc[j] = fmaf(acc[j], scale, p * x[j]);
        m = mnew;
    }

    // Combine warps within the CTA
    __shared__ float s_acc[WARPS][D_DIM];
    __shared__ float s_m[WARPS], s_l[WARPS];
#pragma unroll
    for (int j = 0; j < 8; j++) s_acc[w][lane * 8 + j] = acc[j];
    if (lane == 0) { s_m[w] = m; s_l[w] = l; }
    __syncthreads();

    float M = -1e30f;
#pragma unroll
    for (int i = 0; i < WARPS; i++) M = fmaxf(M, s_m[i]);

    const int t = threadIdx.x;  // 0..255 == d index
    float a = 0.0f;
#pragma unroll
    for (int i = 0; i < WARPS; i++) a += __expf(s_m[i] - M) * s_acc[i][t];

    float* o = g_scratch + ((long long)(b * NSPLIT + split)) * (D_DIM + 2);
    o[t] = a;
    if (t == 0) {
        float L = 0.0f;
#pragma unroll
        for (int i = 0; i < WARPS; i++) L += __expf(s_m[i] - M) * s_l[i];
        o[D_DIM]     = M;
        o[D_DIM + 1] = L;
    }
}

__global__ __launch_bounds__(D_DIM) void ta_pass2(float* __restrict__ out, int B)
{
    const int b = blockIdx.x;
    const int t = threadIdx.x;  // d index
    const float* sc = g_scratch + (long long)b * NSPLIT * (D_DIM + 2);

    float M = -1e30f;
#pragma unroll
    for (int i = 0; i < NSPLIT; i++) M = fmaxf(M, sc[i * (D_DIM + 2) + D_DIM]);

    float L = 0.0f, a = 0.0f;
#pragma unroll
    for (int i = 0; i < NSPLIT; i++) {
        float e = __expf(sc[i * (D_DIM + 2) + D_DIM] - M);
        L += e * sc[i * (D_DIM + 2) + D_DIM + 1];
        a += e * sc[i * (D_DIM + 2) + t];
    }
    out[t * B + b] = a / L;  // out is [D, B]
}

extern "C" void kernel_launch(void* const* d_in, const int* in_sizes, int n_in,
                              void* d_out, int out_size)
{
    const float* enc = (const float*)d_in[0];
    const float* Ww  = (const float*)d_in[1];
    const float* Wb  = (const float*)d_in[2];
    const float* ut  = (const float*)d_in[3];
    float* out = (float*)d_out;

    const int D = in_sizes[1];           // 256
    const int B = out_size / D;          // 64
    const int S = in_sizes[0] / (B * D); // 4096

    dim3 grid1(NSPLIT, B);
    ta_pass1<<<grid1, THREADS>>>(enc, Ww, Wb, ut, S);
    ta_pass2<<<B, D_DIM>>>(out, B);
}